// round 1
// baseline (speedup 1.0000x reference)
#include <cuda_runtime.h>
#include <math.h>

#define BB 4
#define SS 2048
#define DD 1024
#define HH 16
#define HDIM 64
#define NT (BB*SS)   // 8192 tokens

// Scratch (static device globals — allocation-free)
__device__ float g_q[(size_t)BB*HH*SS*HDIM];   // [b,h,s,hd]
__device__ float g_k[(size_t)BB*HH*SS*HDIM];
__device__ float g_v[(size_t)BB*HH*SS*HDIM];
__device__ float g_att[(size_t)NT*DD];          // [t, d]

// ---------------------------------------------------------------------------
// Kernel 1: QKV projection + bias + fused RoPE, writes [B,H,S,HD] scratch.
// out[t,n] = sum_k x[t,k] * W[n,k] + b[n]   (W row-major [D,D])
// Tiles: 64(M) x 64(N) x 16(K), 16x16 threads, 4x4 per thread (stride-16).
// ---------------------------------------------------------------------------
__global__ void qkv_kernel(const float* __restrict__ x,
                           const float* __restrict__ Wq, const float* __restrict__ bq,
                           const float* __restrict__ Wk, const float* __restrict__ bk,
                           const float* __restrict__ Wv, const float* __restrict__ bv,
                           const float* __restrict__ cosT, const float* __restrict__ sinT)
{
    const int z = blockIdx.z;
    const float* __restrict__ Wp = (z == 0) ? Wq : (z == 1) ? Wk : Wv;
    const float* __restrict__ bp = (z == 0) ? bq : (z == 1) ? bk : bv;
    float* __restrict__ dst = (z == 0) ? g_q : (z == 1) ? g_k : g_v;

    __shared__ float As[16][65];   // [k][m]
    __shared__ float Bs[16][65];   // [k][n]

    const int tx = threadIdx.x, ty = threadIdx.y;
    const int tid = ty * 16 + tx;
    const int t0 = blockIdx.y * 64;
    const int n0 = blockIdx.x * 64;

    float acc[4][4] = {};

    for (int k0 = 0; k0 < DD; k0 += 16) {
        #pragma unroll
        for (int p = 0; p < 4; ++p) {
            int idx = tid + p * 256;        // 0..1023
            int row = idx >> 4;             // 0..63
            int col = idx & 15;             // 0..15 (k)
            As[col][row] = x [(size_t)(t0 + row) * DD + (k0 + col)];
            Bs[col][row] = Wp[(size_t)(n0 + row) * DD + (k0 + col)];
        }
        __syncthreads();
        #pragma unroll
        for (int kk = 0; kk < 16; ++kk) {
            float a[4], b[4];
            #pragma unroll
            for (int i = 0; i < 4; ++i) a[i] = As[kk][ty + 16 * i];
            #pragma unroll
            for (int j = 0; j < 4; ++j) b[j] = Bs[kk][tx + 16 * j];
            #pragma unroll
            for (int i = 0; i < 4; ++i)
                #pragma unroll
                for (int j = 0; j < 4; ++j)
                    acc[i][j] = fmaf(a[i], b[j], acc[i][j]);
        }
        __syncthreads();
    }

    const int h = n0 >> 6;   // N-tile == one head
    #pragma unroll
    for (int i = 0; i < 4; ++i) {
        int t = t0 + ty + 16 * i;
        int b = t >> 11;            // /2048
        int s = t & (SS - 1);
        #pragma unroll
        for (int j = 0; j < 4; ++j)
            acc[i][j] += bp[n0 + tx + 16 * j];

        if (z < 2) {
            // RoPE: pairs (hd, hd+32) are registers (j, j+2)
            #pragma unroll
            for (int j = 0; j < 2; ++j) {
                int hd0 = tx + 16 * j;
                float c0 = cosT[s * HDIM + hd0];
                float s0 = sinT[s * HDIM + hd0];
                float c1 = cosT[s * HDIM + hd0 + 32];
                float s1 = sinT[s * HDIM + hd0 + 32];
                float v0 = acc[i][j], v1 = acc[i][j + 2];
                acc[i][j]     = v0 * c0 - v1 * s0;
                acc[i][j + 2] = v1 * c1 + v0 * s1;
            }
        }
        size_t base = (((size_t)b * HH + h) * SS + s) * HDIM;
        #pragma unroll
        for (int j = 0; j < 4; ++j)
            dst[base + tx + 16 * j] = acc[i][j];
    }
}

// ---------------------------------------------------------------------------
// Kernel 2: flash-style causal attention. grid = (32 q-tiles, 64 b*h).
// Dynamic smem: Qs,Ks,Vs,Ps each 64x65 floats.
// ---------------------------------------------------------------------------
__global__ void attn_kernel()
{
    extern __shared__ float sm[];
    float* Qs = sm;
    float* Ks = sm + 64 * 65;
    float* Vs = sm + 2 * 64 * 65;
    float* Ps = sm + 3 * 64 * 65;

    const int bh = blockIdx.y;       // 0..63
    const int qb = blockIdx.x;       // 0..31
    const int q0 = qb * 64;
    const float* __restrict__ qptr = g_q + (size_t)bh * SS * HDIM;
    const float* __restrict__ kptr = g_k + (size_t)bh * SS * HDIM;
    const float* __restrict__ vptr = g_v + (size_t)bh * SS * HDIM;

    const int tx = threadIdx.x, ty = threadIdx.y;
    const int tid = ty * 16 + tx;

    // Load Q tile [64 q][64 hd]
    #pragma unroll
    for (int p = 0; p < 16; ++p) {
        int idx = tid + p * 256;
        int row = idx >> 6;
        int col = idx & 63;
        Qs[row * 65 + col] = qptr[(size_t)(q0 + row) * HDIM + col];
    }

    float m[4], l[4], o[4][4];
    #pragma unroll
    for (int i = 0; i < 4; ++i) {
        m[i] = -INFINITY; l[i] = 0.f;
        #pragma unroll
        for (int j = 0; j < 4; ++j) o[i][j] = 0.f;
    }

    const float scale = 0.125f;  // 1/sqrt(64)

    for (int kb = 0; kb <= qb; ++kb) {
        const int k0 = kb * 64;
        __syncthreads();
        #pragma unroll
        for (int p = 0; p < 16; ++p) {
            int idx = tid + p * 256;
            int row = idx >> 6;
            int col = idx & 63;
            Ks[row * 65 + col] = kptr[(size_t)(k0 + row) * HDIM + col];
            Vs[row * 65 + col] = vptr[(size_t)(k0 + row) * HDIM + col];
        }
        __syncthreads();

        // S = Q K^T (64x64 tile), thread owns rows ty+16i, cols tx+16j
        float sc[4][4] = {};
        #pragma unroll 8
        for (int kk = 0; kk < 64; ++kk) {
            float a[4], b[4];
            #pragma unroll
            for (int i = 0; i < 4; ++i) a[i] = Qs[(ty + 16 * i) * 65 + kk];
            #pragma unroll
            for (int j = 0; j < 4; ++j) b[j] = Ks[(tx + 16 * j) * 65 + kk];
            #pragma unroll
            for (int i = 0; i < 4; ++i)
                #pragma unroll
                for (int j = 0; j < 4; ++j)
                    sc[i][j] = fmaf(a[i], b[j], sc[i][j]);
        }

        // scale + causal mask (diagonal block only)
        if (kb == qb) {
            #pragma unroll
            for (int i = 0; i < 4; ++i) {
                int qrow = ty + 16 * i;
                #pragma unroll
                for (int j = 0; j < 4; ++j) {
                    int kcol = tx + 16 * j;
                    sc[i][j] = (kcol > qrow) ? -INFINITY : sc[i][j] * scale;
                }
            }
        } else {
            #pragma unroll
            for (int i = 0; i < 4; ++i)
                #pragma unroll
                for (int j = 0; j < 4; ++j)
                    sc[i][j] *= scale;
        }

        // Online softmax per row (reduce across 16 lanes sharing a row group)
        #pragma unroll
        for (int i = 0; i < 4; ++i) {
            float rm = fmaxf(fmaxf(sc[i][0], sc[i][1]), fmaxf(sc[i][2], sc[i][3]));
            #pragma unroll
            for (int off = 8; off >= 1; off >>= 1)
                rm = fmaxf(rm, __shfl_xor_sync(0xffffffffu, rm, off));
            float mn = fmaxf(m[i], rm);
            float p0[4]; float rs = 0.f;
            #pragma unroll
            for (int j = 0; j < 4; ++j) { p0[j] = __expf(sc[i][j] - mn); rs += p0[j]; }
            #pragma unroll
            for (int off = 8; off >= 1; off >>= 1)
                rs += __shfl_xor_sync(0xffffffffu, rs, off);
            float alpha = __expf(m[i] - mn);
            l[i] = l[i] * alpha + rs;
            m[i] = mn;
            #pragma unroll
            for (int j = 0; j < 4; ++j) o[i][j] *= alpha;
            #pragma unroll
            for (int j = 0; j < 4; ++j)
                Ps[(ty + 16 * i) * 65 + tx + 16 * j] = p0[j];
        }
        __syncthreads();

        // O += P V   (P[64q x 64k] * V[64k x 64hd])
        #pragma unroll 8
        for (int kk = 0; kk < 64; ++kk) {
            float a[4], b[4];
            #pragma unroll
            for (int i = 0; i < 4; ++i) a[i] = Ps[(ty + 16 * i) * 65 + kk];
            #pragma unroll
            for (int j = 0; j < 4; ++j) b[j] = Vs[kk * 65 + tx + 16 * j];
            #pragma unroll
            for (int i = 0; i < 4; ++i)
                #pragma unroll
                for (int j = 0; j < 4; ++j)
                    o[i][j] = fmaf(a[i], b[j], o[i][j]);
        }
    }

    // Normalize + write to [t, d] layout
    const int b = bh >> 4;       // /16
    const int h = bh & 15;
    #pragma unroll
    for (int i = 0; i < 4; ++i) {
        float inv = 1.f / l[i];
        int s = q0 + ty + 16 * i;
        size_t base = ((size_t)(b * SS + s)) * DD + h * HDIM;
        #pragma unroll
        for (int j = 0; j < 4; ++j)
            g_att[base + tx + 16 * j] = o[i][j] * inv;
    }
}

// ---------------------------------------------------------------------------
// Kernel 3: output projection. out[t,n] = sum_k att[t,k]*Wo[n,k] + bo[n]
// ---------------------------------------------------------------------------
__global__ void out_proj_kernel(const float* __restrict__ Wo,
                                const float* __restrict__ bo,
                                float* __restrict__ out)
{
    __shared__ float As[16][65];
    __shared__ float Bs[16][65];

    const int tx = threadIdx.x, ty = threadIdx.y;
    const int tid = ty * 16 + tx;
    const int t0 = blockIdx.y * 64;
    const int n0 = blockIdx.x * 64;

    float acc[4][4] = {};

    for (int k0 = 0; k0 < DD; k0 += 16) {
        #pragma unroll
        for (int p = 0; p < 4; ++p) {
            int idx = tid + p * 256;
            int row = idx >> 4;
            int col = idx & 15;
            As[col][row] = g_att[(size_t)(t0 + row) * DD + (k0 + col)];
            Bs[col][row] = Wo   [(size_t)(n0 + row) * DD + (k0 + col)];
        }
        __syncthreads();
        #pragma unroll
        for (int kk = 0; kk < 16; ++kk) {
            float a[4], b[4];
            #pragma unroll
            for (int i = 0; i < 4; ++i) a[i] = As[kk][ty + 16 * i];
            #pragma unroll
            for (int j = 0; j < 4; ++j) b[j] = Bs[kk][tx + 16 * j];
            #pragma unroll
            for (int i = 0; i < 4; ++i)
                #pragma unroll
                for (int j = 0; j < 4; ++j)
                    acc[i][j] = fmaf(a[i], b[j], acc[i][j]);
        }
        __syncthreads();
    }

    #pragma unroll
    for (int i = 0; i < 4; ++i) {
        int t = t0 + ty + 16 * i;
        #pragma unroll
        for (int j = 0; j < 4; ++j) {
            int n = n0 + tx + 16 * j;
            out[(size_t)t * DD + n] = acc[i][j] + bo[n];
        }
    }
}

// ---------------------------------------------------------------------------
extern "C" void kernel_launch(void* const* d_in, const int* in_sizes, int n_in,
                              void* d_out, int out_size)
{
    const float* x    = (const float*)d_in[0];
    const float* cosT = (const float*)d_in[1];
    const float* sinT = (const float*)d_in[2];
    // d_in[3] = attn_mask (causal — unused, mask applied analytically)
    const float* Wq = (const float*)d_in[4];
    const float* bq = (const float*)d_in[5];
    const float* Wk = (const float*)d_in[6];
    const float* bk = (const float*)d_in[7];
    const float* Wv = (const float*)d_in[8];
    const float* bv = (const float*)d_in[9];
    const float* Wo = (const float*)d_in[10];
    const float* bo = (const float*)d_in[11];
    float* out = (float*)d_out;

    dim3 blk(16, 16);

    // 1) QKV projections + RoPE
    qkv_kernel<<<dim3(DD / 64, NT / 64, 3), blk>>>(x, Wq, bq, Wk, bk, Wv, bv, cosT, sinT);

    // 2) causal flash attention
    size_t smem = (size_t)4 * 64 * 65 * sizeof(float);   // 66560 B
    cudaFuncSetAttribute(attn_kernel, cudaFuncAttributeMaxDynamicSharedMemorySize, (int)smem);
    attn_kernel<<<dim3(SS / 64, BB * HH), blk, smem>>>();

    // 3) output projection
    out_proj_kernel<<<dim3(DD / 64, NT / 64), blk>>>(Wo, bo, out);
}

// round 2
// speedup vs baseline: 1.4080x; 1.4080x over previous
#include <cuda_runtime.h>
#include <math.h>

#define BB 4
#define SS 2048
#define DD 1024
#define HH 16
#define HDIM 64
#define NT (BB*SS)   // 8192 tokens
#define GP 132       // GEMM smem pitch ([k][m] layout, deg-2 store conflicts only)
#define AP 65        // attention smem pitch (conflict-free strided reads)

// Scratch (static device globals — allocation-free)
__device__ float g_q[(size_t)BB*HH*SS*HDIM];   // [b,h,s,hd]
__device__ float g_k[(size_t)BB*HH*SS*HDIM];
__device__ float g_v[(size_t)BB*HH*SS*HDIM];
__device__ float g_att[(size_t)NT*DD];          // [t, d]

// ---------------------------------------------------------------------------
// Kernel 1: QKV projection + bias + fused RoPE.
// out[t,n] = sum_k x[t,k]*W[n,k] + b[n].
// 128x128x16 tiles, 256 threads, 8x8 per thread (rows contiguous, cols stride-16
// so RoPE partners (hd, hd+32) sit in registers j and j+2). Double-buffered smem.
// ---------------------------------------------------------------------------
__global__ __launch_bounds__(256, 2) void qkv_kernel(
    const float* __restrict__ x,
    const float* __restrict__ Wq, const float* __restrict__ bq,
    const float* __restrict__ Wk, const float* __restrict__ bk,
    const float* __restrict__ Wv, const float* __restrict__ bv,
    const float* __restrict__ cosT, const float* __restrict__ sinT)
{
    __shared__ float As[2][16*GP];   // [k][m]
    __shared__ float Bs[2][16*GP];   // [k][n]

    const int z = blockIdx.z;
    const float* __restrict__ Wp = (z==0) ? Wq : (z==1) ? Wk : Wv;
    const float* __restrict__ bp = (z==0) ? bq : (z==1) ? bk : bv;
    float* __restrict__ dst      = (z==0) ? g_q : (z==1) ? g_k : g_v;

    const int tid = threadIdx.x;
    const int tx = tid & 15, ty = tid >> 4;
    const int t0 = blockIdx.y * 128;
    const int n0 = blockIdx.x * 128;

    const int lr = tid >> 2;   // 0..63 (row within 64-row half)
    const int lq = tid & 3;    // 0..3  (float4 quad within 16-wide k)

    float acc[8][8] = {};
    float4 pa[2], pb[2];

    // preload k-tile 0
    #pragma unroll
    for (int p = 0; p < 2; ++p) {
        pa[p] = *(const float4*)&x [(size_t)(t0 + lr + 64*p)*DD + lq*4];
        pb[p] = *(const float4*)&Wp[(size_t)(n0 + lr + 64*p)*DD + lq*4];
    }
    #pragma unroll
    for (int p = 0; p < 2; ++p) {
        float va[4] = {pa[p].x, pa[p].y, pa[p].z, pa[p].w};
        float vb[4] = {pb[p].x, pb[p].y, pb[p].z, pb[p].w};
        #pragma unroll
        for (int c = 0; c < 4; ++c) {
            As[0][(lq*4+c)*GP + lr + 64*p] = va[c];
            Bs[0][(lq*4+c)*GP + lr + 64*p] = vb[c];
        }
    }
    __syncthreads();

    for (int ks = 0; ks < DD/16; ++ks) {
        const int buf = ks & 1;
        if (ks + 1 < DD/16) {
            const int k0 = (ks+1)*16;
            #pragma unroll
            for (int p = 0; p < 2; ++p) {
                pa[p] = *(const float4*)&x [(size_t)(t0 + lr + 64*p)*DD + k0 + lq*4];
                pb[p] = *(const float4*)&Wp[(size_t)(n0 + lr + 64*p)*DD + k0 + lq*4];
            }
        }
        #pragma unroll
        for (int kk = 0; kk < 16; ++kk) {
            float4 a0 = *(const float4*)&As[buf][kk*GP + ty*8];
            float4 a1 = *(const float4*)&As[buf][kk*GP + ty*8 + 4];
            float a[8] = {a0.x,a0.y,a0.z,a0.w, a1.x,a1.y,a1.z,a1.w};
            float b[8];
            #pragma unroll
            for (int j = 0; j < 8; ++j) b[j] = Bs[buf][kk*GP + tx + 16*j];
            #pragma unroll
            for (int i = 0; i < 8; ++i)
                #pragma unroll
                for (int j = 0; j < 8; ++j)
                    acc[i][j] = fmaf(a[i], b[j], acc[i][j]);
        }
        if (ks + 1 < DD/16) {
            const int nb = buf ^ 1;
            #pragma unroll
            for (int p = 0; p < 2; ++p) {
                float va[4] = {pa[p].x, pa[p].y, pa[p].z, pa[p].w};
                float vb[4] = {pb[p].x, pb[p].y, pb[p].z, pb[p].w};
                #pragma unroll
                for (int c = 0; c < 4; ++c) {
                    As[nb][(lq*4+c)*GP + lr + 64*p] = va[c];
                    Bs[nb][(lq*4+c)*GP + lr + 64*p] = vb[c];
                }
            }
        }
        __syncthreads();
    }

    // Epilogue: bias + RoPE + scatter to [b,h,s,hd]
    float bb[8];
    #pragma unroll
    for (int j = 0; j < 8; ++j) bb[j] = bp[n0 + tx + 16*j];

    #pragma unroll
    for (int i = 0; i < 8; ++i) {
        int t = t0 + ty*8 + i;
        int b = t >> 11;
        int s = t & (SS - 1);
        #pragma unroll
        for (int j = 0; j < 8; ++j) acc[i][j] += bb[j];

        if (z < 2) {
            const int pj[4] = {0, 1, 4, 5};
            #pragma unroll
            for (int pi = 0; pi < 4; ++pi) {
                int j = pj[pi];
                int ch = (tx + 16*j) & 63;   // < 32
                float c0 = cosT[s*HDIM + ch];
                float s0 = sinT[s*HDIM + ch];
                float c1 = cosT[s*HDIM + ch + 32];
                float s1 = sinT[s*HDIM + ch + 32];
                float v0 = acc[i][j], v1 = acc[i][j+2];
                acc[i][j]   = v0*c0 - v1*s0;
                acc[i][j+2] = v1*c1 + v0*s1;
            }
        }
        #pragma unroll
        for (int j = 0; j < 8; ++j) {
            int n = n0 + tx + 16*j;
            int h = n >> 6;
            int hd = n & 63;
            dst[(((size_t)b*HH + h)*SS + s)*HDIM + hd] = acc[i][j];
        }
    }
}

// ---------------------------------------------------------------------------
// Kernel 2: flash causal attention. 128q x 64k tiles, 256 threads, 8x4/thread.
// All smem tiles in natural [row][hd] layout with pitch 65 (conflict-free).
// ---------------------------------------------------------------------------
__global__ __launch_bounds__(256, 2) void attn_kernel()
{
    extern __shared__ float sm[];
    float* Qs = sm;               // [128][AP]
    float* Ks = Qs + 128*AP;      // [64][AP]
    float* Vs = Ks + 64*AP;       // [64][AP]
    float* Ps = Vs + 64*AP;       // [128][AP]

    const int tid = threadIdx.x;
    const int tx = tid & 15, ty = tid >> 4;
    const int bh = blockIdx.y;
    const int qt = gridDim.x - 1 - blockIdx.x;   // long tiles first
    const int q0 = qt * 128;

    const float* __restrict__ qptr = g_q + (size_t)bh * SS * HDIM;
    const float* __restrict__ kptr = g_k + (size_t)bh * SS * HDIM;
    const float* __restrict__ vptr = g_v + (size_t)bh * SS * HDIM;

    // Load Q tile [128][64]
    #pragma unroll
    for (int p = 0; p < 8; ++p) {
        int idx = tid + p*256;
        int row = idx >> 4;
        int qd  = idx & 15;
        float4 v = *(const float4*)&qptr[(size_t)(q0 + row)*HDIM + qd*4];
        float vv[4] = {v.x, v.y, v.z, v.w};
        #pragma unroll
        for (int c = 0; c < 4; ++c) Qs[row*AP + qd*4 + c] = vv[c];
    }

    float m[8], l[8], o[8][4];
    #pragma unroll
    for (int i = 0; i < 8; ++i) {
        m[i] = -INFINITY; l[i] = 0.f;
        #pragma unroll
        for (int j = 0; j < 4; ++j) o[i][j] = 0.f;
    }

    const float scale = 0.125f;
    const int nkb = 2*qt + 2;   // key blocks of 64 covering [0, q0+128)

    for (int kb = 0; kb < nkb; ++kb) {
        const int k0 = kb * 64;
        __syncthreads();
        #pragma unroll
        for (int p = 0; p < 4; ++p) {
            int idx = tid + p*256;
            int row = idx >> 4;
            int qd  = idx & 15;
            float4 kv = *(const float4*)&kptr[(size_t)(k0 + row)*HDIM + qd*4];
            float4 vv = *(const float4*)&vptr[(size_t)(k0 + row)*HDIM + qd*4];
            float ka[4] = {kv.x, kv.y, kv.z, kv.w};
            float va[4] = {vv.x, vv.y, vv.z, vv.w};
            #pragma unroll
            for (int c = 0; c < 4; ++c) {
                Ks[row*AP + qd*4 + c] = ka[c];
                Vs[row*AP + qd*4 + c] = va[c];
            }
        }
        __syncthreads();

        // S = Q K^T
        float sc[8][4] = {};
        #pragma unroll 4
        for (int kk = 0; kk < HDIM; ++kk) {
            float a[8], b[4];
            #pragma unroll
            for (int i = 0; i < 8; ++i) a[i] = Qs[(ty*8+i)*AP + kk];
            #pragma unroll
            for (int j = 0; j < 4; ++j) b[j] = Ks[(tx+16*j)*AP + kk];
            #pragma unroll
            for (int i = 0; i < 8; ++i)
                #pragma unroll
                for (int j = 0; j < 4; ++j)
                    sc[i][j] = fmaf(a[i], b[j], sc[i][j]);
        }

        // scale + causal mask (only boundary blocks)
        const bool boundary = (k0 + 63 > q0);
        #pragma unroll
        for (int i = 0; i < 8; ++i) {
            int qrow = q0 + ty*8 + i;
            #pragma unroll
            for (int j = 0; j < 4; ++j) {
                int kcol = k0 + tx + 16*j;
                sc[i][j] = (boundary && kcol > qrow) ? -INFINITY : sc[i][j]*scale;
            }
        }

        // online softmax (row spread over 16 tx lanes)
        #pragma unroll
        for (int i = 0; i < 8; ++i) {
            float rm = fmaxf(fmaxf(sc[i][0], sc[i][1]), fmaxf(sc[i][2], sc[i][3]));
            #pragma unroll
            for (int off = 8; off >= 1; off >>= 1)
                rm = fmaxf(rm, __shfl_xor_sync(0xffffffffu, rm, off));
            float mn = fmaxf(m[i], rm);
            float p0[4]; float rs = 0.f;
            #pragma unroll
            for (int j = 0; j < 4; ++j) { p0[j] = __expf(sc[i][j] - mn); rs += p0[j]; }
            #pragma unroll
            for (int off = 8; off >= 1; off >>= 1)
                rs += __shfl_xor_sync(0xffffffffu, rs, off);
            float alpha = __expf(m[i] - mn);
            l[i] = l[i]*alpha + rs;
            m[i] = mn;
            #pragma unroll
            for (int j = 0; j < 4; ++j) o[i][j] *= alpha;
            #pragma unroll
            for (int j = 0; j < 4; ++j)
                Ps[(ty*8+i)*AP + tx + 16*j] = p0[j];
        }
        __syncthreads();

        // O += P V
        #pragma unroll 4
        for (int kk = 0; kk < 64; ++kk) {
            float a[8], b[4];
            #pragma unroll
            for (int i = 0; i < 8; ++i) a[i] = Ps[(ty*8+i)*AP + kk];
            #pragma unroll
            for (int j = 0; j < 4; ++j) b[j] = Vs[kk*AP + tx + 16*j];
            #pragma unroll
            for (int i = 0; i < 8; ++i)
                #pragma unroll
                for (int j = 0; j < 4; ++j)
                    o[i][j] = fmaf(a[i], b[j], o[i][j]);
        }
    }

    // normalize + write [t, d]
    const int b = bh >> 4;
    const int h = bh & 15;
    #pragma unroll
    for (int i = 0; i < 8; ++i) {
        float inv = 1.f / l[i];
        int s = q0 + ty*8 + i;
        size_t base = ((size_t)(b*SS + s))*DD + h*HDIM;
        #pragma unroll
        for (int j = 0; j < 4; ++j)
            g_att[base + tx + 16*j] = o[i][j] * inv;
    }
}

// ---------------------------------------------------------------------------
// Kernel 3: output projection (same GEMM, no RoPE), writes d_out.
// ---------------------------------------------------------------------------
__global__ __launch_bounds__(256, 2) void out_proj_kernel(
    const float* __restrict__ Wo,
    const float* __restrict__ bo,
    float* __restrict__ out)
{
    __shared__ float As[2][16*GP];
    __shared__ float Bs[2][16*GP];

    const int tid = threadIdx.x;
    const int tx = tid & 15, ty = tid >> 4;
    const int t0 = blockIdx.y * 128;
    const int n0 = blockIdx.x * 128;

    const int lr = tid >> 2;
    const int lq = tid & 3;

    float acc[8][8] = {};
    float4 pa[2], pb[2];

    #pragma unroll
    for (int p = 0; p < 2; ++p) {
        pa[p] = *(const float4*)&g_att[(size_t)(t0 + lr + 64*p)*DD + lq*4];
        pb[p] = *(const float4*)&Wo   [(size_t)(n0 + lr + 64*p)*DD + lq*4];
    }
    #pragma unroll
    for (int p = 0; p < 2; ++p) {
        float va[4] = {pa[p].x, pa[p].y, pa[p].z, pa[p].w};
        float vb[4] = {pb[p].x, pb[p].y, pb[p].z, pb[p].w};
        #pragma unroll
        for (int c = 0; c < 4; ++c) {
            As[0][(lq*4+c)*GP + lr + 64*p] = va[c];
            Bs[0][(lq*4+c)*GP + lr + 64*p] = vb[c];
        }
    }
    __syncthreads();

    for (int ks = 0; ks < DD/16; ++ks) {
        const int buf = ks & 1;
        if (ks + 1 < DD/16) {
            const int k0 = (ks+1)*16;
            #pragma unroll
            for (int p = 0; p < 2; ++p) {
                pa[p] = *(const float4*)&g_att[(size_t)(t0 + lr + 64*p)*DD + k0 + lq*4];
                pb[p] = *(const float4*)&Wo   [(size_t)(n0 + lr + 64*p)*DD + k0 + lq*4];
            }
        }
        #pragma unroll
        for (int kk = 0; kk < 16; ++kk) {
            float4 a0 = *(const float4*)&As[buf][kk*GP + ty*8];
            float4 a1 = *(const float4*)&As[buf][kk*GP + ty*8 + 4];
            float a[8] = {a0.x,a0.y,a0.z,a0.w, a1.x,a1.y,a1.z,a1.w};
            float b[8];
            #pragma unroll
            for (int j = 0; j < 8; ++j) b[j] = Bs[buf][kk*GP + tx + 16*j];
            #pragma unroll
            for (int i = 0; i < 8; ++i)
                #pragma unroll
                for (int j = 0; j < 8; ++j)
                    acc[i][j] = fmaf(a[i], b[j], acc[i][j]);
        }
        if (ks + 1 < DD/16) {
            const int nb = buf ^ 1;
            #pragma unroll
            for (int p = 0; p < 2; ++p) {
                float va[4] = {pa[p].x, pa[p].y, pa[p].z, pa[p].w};
                float vb[4] = {pb[p].x, pb[p].y, pb[p].z, pb[p].w};
                #pragma unroll
                for (int c = 0; c < 4; ++c) {
                    As[nb][(lq*4+c)*GP + lr + 64*p] = va[c];
                    Bs[nb][(lq*4+c)*GP + lr + 64*p] = vb[c];
                }
            }
        }
        __syncthreads();
    }

    float bb[8];
    #pragma unroll
    for (int j = 0; j < 8; ++j) bb[j] = bo[n0 + tx + 16*j];

    #pragma unroll
    for (int i = 0; i < 8; ++i) {
        int t = t0 + ty*8 + i;
        #pragma unroll
        for (int j = 0; j < 8; ++j) {
            int n = n0 + tx + 16*j;
            out[(size_t)t*DD + n] = acc[i][j] + bb[j];
        }
    }
}

// ---------------------------------------------------------------------------
extern "C" void kernel_launch(void* const* d_in, const int* in_sizes, int n_in,
                              void* d_out, int out_size)
{
    const float* x    = (const float*)d_in[0];
    const float* cosT = (const float*)d_in[1];
    const float* sinT = (const float*)d_in[2];
    // d_in[3] = attn_mask (causal — applied analytically)
    const float* Wq = (const float*)d_in[4];
    const float* bq = (const float*)d_in[5];
    const float* Wk = (const float*)d_in[6];
    const float* bk = (const float*)d_in[7];
    const float* Wv = (const float*)d_in[8];
    const float* bv = (const float*)d_in[9];
    const float* Wo = (const float*)d_in[10];
    const float* bo = (const float*)d_in[11];
    float* out = (float*)d_out;

    // 1) QKV + RoPE
    qkv_kernel<<<dim3(DD/128, NT/128, 3), 256>>>(x, Wq, bq, Wk, bk, Wv, bv, cosT, sinT);

    // 2) causal flash attention
    size_t smem = (size_t)(128*AP + 64*AP + 64*AP + 128*AP) * sizeof(float);  // 99840 B
    cudaFuncSetAttribute(attn_kernel, cudaFuncAttributeMaxDynamicSharedMemorySize, (int)smem);
    attn_kernel<<<dim3(SS/128, BB*HH), 256, smem>>>();

    // 3) output projection
    out_proj_kernel<<<dim3(DD/128, NT/128), 256>>>(Wo, bo, out);
}

// round 4
// speedup vs baseline: 1.9363x; 1.3753x over previous
#include <cuda_runtime.h>
#include <cuda_bf16.h>
#include <math.h>

#define BB 4
#define SS 2048
#define DD 1024
#define HH 16
#define HDIM 64
#define NT (BB*SS)   // 8192 tokens
#define AP 65        // attention smem pitch
#define PA 40        // gemm smem pitch (bf16 elems), conflict-free fragment loads

// Scratch (static device globals — allocation-free)
__device__ float g_q[(size_t)BB*HH*SS*HDIM];   // [b,h,s,hd]
__device__ float g_k[(size_t)BB*HH*SS*HDIM];
__device__ float g_v[(size_t)BB*HH*SS*HDIM];
__device__ float g_att[(size_t)NT*DD];          // [t, d]

#define MMA_BF16(d, a, b0, b1)                                             \
    asm("mma.sync.aligned.m16n8k16.row.col.f32.bf16.bf16.f32 "             \
        "{%0,%1,%2,%3}, {%4,%5,%6,%7}, {%8,%9}, {%0,%1,%2,%3};"            \
        : "+f"(d[0]), "+f"(d[1]), "+f"(d[2]), "+f"(d[3])                   \
        : "r"(a[0]), "r"(a[1]), "r"(a[2]), "r"(a[3]), "r"(b0), "r"(b1))

// ---------------------------------------------------------------------------
// bf16-split GEMM mainloop: out[t,n] = sum_k A[t,k]*W[n,k]
// 128x128 block tile, 256 threads (8 warps: 4M x 2N), warp = 32x64.
// A,W converted fp32 -> bf16 hi/lo on the fly. acc[2][8][4] fp32 fragments.
// ---------------------------------------------------------------------------
__device__ __forceinline__ void run_gemm(
    const float* __restrict__ Ag, const float* __restrict__ Wg,
    int t0, int n0,
    __nv_bfloat16* __restrict__ Ah, __nv_bfloat16* __restrict__ Al,
    __nv_bfloat16* __restrict__ Bh, __nv_bfloat16* __restrict__ Bl,
    float acc[2][8][4])
{
    const int tid  = threadIdx.x;
    const int lane = tid & 31;
    const int warp = tid >> 5;
    const int wm   = warp & 3;    // 0..3  -> rows wm*32
    const int wn   = warp >> 2;   // 0..1  -> cols wn*64
    const int lrow = tid >> 3;    // 0..31 with p offset -> gmem row
    const int lc4  = tid & 7;     // float4 index within 32-wide k

    float4 ra[4], rb[4];

    // prefetch chunk 0
    #pragma unroll
    for (int p = 0; p < 4; ++p) {
        int row = lrow + p * 32;
        ra[p] = *(const float4*)&Ag[(size_t)(t0 + row) * DD + lc4 * 4];
        rb[p] = *(const float4*)&Wg[(size_t)(n0 + row) * DD + lc4 * 4];
    }

    for (int kc = 0; kc < DD / 32; ++kc) {
        // convert + store current chunk to smem
        #pragma unroll
        for (int p = 0; p < 4; ++p) {
            int row = lrow + p * 32;
            float va[4] = {ra[p].x, ra[p].y, ra[p].z, ra[p].w};
            float vb[4] = {rb[p].x, rb[p].y, rb[p].z, rb[p].w};
            #pragma unroll
            for (int e = 0; e < 2; ++e) {
                __nv_bfloat16 h0 = __float2bfloat16(va[2*e]);
                __nv_bfloat16 h1 = __float2bfloat16(va[2*e+1]);
                __nv_bfloat16 l0 = __float2bfloat16(va[2*e]   - __bfloat162float(h0));
                __nv_bfloat16 l1 = __float2bfloat16(va[2*e+1] - __bfloat162float(h1));
                *(__nv_bfloat162*)&Ah[row*PA + lc4*4 + 2*e] = __nv_bfloat162(h0, h1);
                *(__nv_bfloat162*)&Al[row*PA + lc4*4 + 2*e] = __nv_bfloat162(l0, l1);
                h0 = __float2bfloat16(vb[2*e]);
                h1 = __float2bfloat16(vb[2*e+1]);
                l0 = __float2bfloat16(vb[2*e]   - __bfloat162float(h0));
                l1 = __float2bfloat16(vb[2*e+1] - __bfloat162float(h1));
                *(__nv_bfloat162*)&Bh[row*PA + lc4*4 + 2*e] = __nv_bfloat162(h0, h1);
                *(__nv_bfloat162*)&Bl[row*PA + lc4*4 + 2*e] = __nv_bfloat162(l0, l1);
            }
        }
        __syncthreads();

        // prefetch next chunk
        if (kc + 1 < DD / 32) {
            const int k0 = (kc + 1) * 32;
            #pragma unroll
            for (int p = 0; p < 4; ++p) {
                int row = lrow + p * 32;
                ra[p] = *(const float4*)&Ag[(size_t)(t0 + row) * DD + k0 + lc4 * 4];
                rb[p] = *(const float4*)&Wg[(size_t)(n0 + row) * DD + k0 + lc4 * 4];
            }
        }

        // compute: 2 k16-steps
        #pragma unroll
        for (int k16 = 0; k16 < 2; ++k16) {
            const int kb = k16 * 16 + (lane & 3) * 2;
            unsigned ah[2][4], al[2][4];
            #pragma unroll
            for (int am = 0; am < 2; ++am) {
                int r0 = wm * 32 + am * 16 + (lane >> 2);
                ah[am][0] = *(const unsigned*)&Ah[ r0      * PA + kb];
                ah[am][1] = *(const unsigned*)&Ah[(r0 + 8) * PA + kb];
                ah[am][2] = *(const unsigned*)&Ah[ r0      * PA + kb + 8];
                ah[am][3] = *(const unsigned*)&Ah[(r0 + 8) * PA + kb + 8];
                al[am][0] = *(const unsigned*)&Al[ r0      * PA + kb];
                al[am][1] = *(const unsigned*)&Al[(r0 + 8) * PA + kb];
                al[am][2] = *(const unsigned*)&Al[ r0      * PA + kb + 8];
                al[am][3] = *(const unsigned*)&Al[(r0 + 8) * PA + kb + 8];
            }
            #pragma unroll
            for (int j = 0; j < 8; ++j) {
                int rn = wn * 64 + j * 8 + (lane >> 2);
                unsigned bh0 = *(const unsigned*)&Bh[rn * PA + kb];
                unsigned bh1 = *(const unsigned*)&Bh[rn * PA + kb + 8];
                unsigned bl0 = *(const unsigned*)&Bl[rn * PA + kb];
                unsigned bl1 = *(const unsigned*)&Bl[rn * PA + kb + 8];
                #pragma unroll
                for (int am = 0; am < 2; ++am) {
                    MMA_BF16(acc[am][j], ah[am], bh0, bh1);
                    MMA_BF16(acc[am][j], ah[am], bl0, bl1);
                    MMA_BF16(acc[am][j], al[am], bh0, bh1);
                }
            }
        }
        __syncthreads();
    }
}

// ---------------------------------------------------------------------------
// Kernel 1: QKV projections + bias + fused RoPE -> [b,h,s,hd] scratch.
// grid = (DD/128, NT/128, 3)
// ---------------------------------------------------------------------------
__global__ __launch_bounds__(256) void qkv_gemm(
    const float* __restrict__ x,
    const float* __restrict__ Wq, const float* __restrict__ bq,
    const float* __restrict__ Wk, const float* __restrict__ bk,
    const float* __restrict__ Wv, const float* __restrict__ bv,
    const float* __restrict__ cosT, const float* __restrict__ sinT)
{
    __shared__ __align__(16) __nv_bfloat16 Ah[128*PA], Al[128*PA], Bh[128*PA], Bl[128*PA];

    const int z = blockIdx.z;
    const float* __restrict__ Wp = (z==0) ? Wq : (z==1) ? Wk : Wv;
    const float* __restrict__ bp = (z==0) ? bq : (z==1) ? bk : bv;
    float* __restrict__ dst      = (z==0) ? g_q : (z==1) ? g_k : g_v;

    const int t0 = blockIdx.y * 128;
    const int n0 = blockIdx.x * 128;
    const int lane = threadIdx.x & 31;
    const int warp = threadIdx.x >> 5;
    const int wm = warp & 3, wn = warp >> 2;

    float acc[2][8][4] = {};
    run_gemm(x, Wp, t0, n0, Ah, Al, Bh, Bl, acc);

    // epilogue: bias + RoPE + scatter
    const int h = (n0 + wn * 64) >> 6;           // head for this warp
    float2 bia[8];
    #pragma unroll
    for (int j = 0; j < 8; ++j)
        bia[j] = *(const float2*)&bp[n0 + wn*64 + j*8 + (lane & 3)*2];

    #pragma unroll
    for (int am = 0; am < 2; ++am) {
        int r0 = t0 + wm*32 + am*16 + (lane >> 2);
        #pragma unroll
        for (int half = 0; half < 2; ++half) {    // c01 (row r0) / c23 (row r0+8)
            int t = r0 + half * 8;
            int b = t >> 11;
            int s = t & (SS - 1);
            size_t base = (((size_t)b*HH + h)*SS + s) * HDIM;
            if (z < 2) {
                #pragma unroll
                for (int j = 0; j < 4; ++j) {
                    int ch = j*8 + (lane & 3)*2;        // < 32
                    float v0a = acc[am][j  ][2*half]   + bia[j].x;
                    float v0b = acc[am][j  ][2*half+1] + bia[j].y;
                    float v1a = acc[am][j+4][2*half]   + bia[j+4].x;
                    float v1b = acc[am][j+4][2*half+1] + bia[j+4].y;
                    float2 c0 = *(const float2*)&cosT[s*HDIM + ch];
                    float2 s0 = *(const float2*)&sinT[s*HDIM + ch];
                    float2 c1 = *(const float2*)&cosT[s*HDIM + ch + 32];
                    float2 s1 = *(const float2*)&sinT[s*HDIM + ch + 32];
                    float2 o0, o1;
                    o0.x = v0a*c0.x - v1a*s0.x;
                    o0.y = v0b*c0.y - v1b*s0.y;
                    o1.x = v1a*c1.x + v0a*s1.x;
                    o1.y = v1b*c1.y + v0b*s1.y;
                    *(float2*)&dst[base + ch]      = o0;
                    *(float2*)&dst[base + ch + 32] = o1;
                }
            } else {
                #pragma unroll
                for (int j = 0; j < 8; ++j) {
                    int ch = j*8 + (lane & 3)*2;        // < 64
                    float2 o;
                    o.x = acc[am][j][2*half]   + bia[j].x;
                    o.y = acc[am][j][2*half+1] + bia[j].y;
                    *(float2*)&dst[base + ch] = o;
                }
            }
        }
    }
}

// ---------------------------------------------------------------------------
// Kernel 3: output projection -> d_out [t, n]. grid = (DD/128, NT/128)
// ---------------------------------------------------------------------------
__global__ __launch_bounds__(256) void out_gemm(
    const float* __restrict__ Wo, const float* __restrict__ bo,
    float* __restrict__ out)
{
    __shared__ __align__(16) __nv_bfloat16 Ah[128*PA], Al[128*PA], Bh[128*PA], Bl[128*PA];

    const int t0 = blockIdx.y * 128;
    const int n0 = blockIdx.x * 128;
    const int lane = threadIdx.x & 31;
    const int warp = threadIdx.x >> 5;
    const int wm = warp & 3, wn = warp >> 2;

    float acc[2][8][4] = {};
    run_gemm(g_att, Wo, t0, n0, Ah, Al, Bh, Bl, acc);

    float2 bia[8];
    #pragma unroll
    for (int j = 0; j < 8; ++j)
        bia[j] = *(const float2*)&bo[n0 + wn*64 + j*8 + (lane & 3)*2];

    #pragma unroll
    for (int am = 0; am < 2; ++am) {
        int r0 = t0 + wm*32 + am*16 + (lane >> 2);
        #pragma unroll
        for (int half = 0; half < 2; ++half) {
            int t = r0 + half * 8;
            #pragma unroll
            for (int j = 0; j < 8; ++j) {
                int n = n0 + wn*64 + j*8 + (lane & 3)*2;
                float2 o;
                o.x = acc[am][j][2*half]   + bia[j].x;
                o.y = acc[am][j][2*half+1] + bia[j].y;
                *(float2*)&out[(size_t)t*DD + n] = o;
            }
        }
    }
}

// ---------------------------------------------------------------------------
// Kernel 2: flash causal attention (unchanged from R1). 128q x 64k tiles.
// ---------------------------------------------------------------------------
__global__ __launch_bounds__(256, 2) void attn_kernel()
{
    extern __shared__ float sm[];
    float* Qs = sm;               // [128][AP]
    float* Ks = Qs + 128*AP;      // [64][AP]
    float* Vs = Ks + 64*AP;       // [64][AP]
    float* Ps = Vs + 64*AP;       // [128][AP]

    const int tid = threadIdx.x;
    const int tx = tid & 15, ty = tid >> 4;
    const int bh = blockIdx.y;
    const int qt = gridDim.x - 1 - blockIdx.x;   // long tiles first
    const int q0 = qt * 128;

    const float* __restrict__ qptr = g_q + (size_t)bh * SS * HDIM;
    const float* __restrict__ kptr = g_k + (size_t)bh * SS * HDIM;
    const float* __restrict__ vptr = g_v + (size_t)bh * SS * HDIM;

    #pragma unroll
    for (int p = 0; p < 8; ++p) {
        int idx = tid + p*256;
        int row = idx >> 4;
        int qd  = idx & 15;
        float4 v = *(const float4*)&qptr[(size_t)(q0 + row)*HDIM + qd*4];
        float vv[4] = {v.x, v.y, v.z, v.w};
        #pragma unroll
        for (int c = 0; c < 4; ++c) Qs[row*AP + qd*4 + c] = vv[c];
    }

    float m[8], l[8], o[8][4];
    #pragma unroll
    for (int i = 0; i < 8; ++i) {
        m[i] = -INFINITY; l[i] = 0.f;
        #pragma unroll
        for (int j = 0; j < 4; ++j) o[i][j] = 0.f;
    }

    const float scale = 0.125f;
    const int nkb = 2*qt + 2;

    for (int kb = 0; kb < nkb; ++kb) {
        const int k0 = kb * 64;
        __syncthreads();
        #pragma unroll
        for (int p = 0; p < 4; ++p) {
            int idx = tid + p*256;
            int row = idx >> 4;
            int qd  = idx & 15;
            float4 kv = *(const float4*)&kptr[(size_t)(k0 + row)*HDIM + qd*4];
            float4 vv = *(const float4*)&vptr[(size_t)(k0 + row)*HDIM + qd*4];
            float ka[4] = {kv.x, kv.y, kv.z, kv.w};
            float va[4] = {vv.x, vv.y, vv.z, vv.w};
            #pragma unroll
            for (int c = 0; c < 4; ++c) {
                Ks[row*AP + qd*4 + c] = ka[c];
                Vs[row*AP + qd*4 + c] = va[c];
            }
        }
        __syncthreads();

        float sc[8][4] = {};
        #pragma unroll 4
        for (int kk = 0; kk < HDIM; ++kk) {
            float a[8], b[4];
            #pragma unroll
            for (int i = 0; i < 8; ++i) a[i] = Qs[(ty*8+i)*AP + kk];
            #pragma unroll
            for (int j = 0; j < 4; ++j) b[j] = Ks[(tx+16*j)*AP + kk];
            #pragma unroll
            for (int i = 0; i < 8; ++i)
                #pragma unroll
                for (int j = 0; j < 4; ++j)
                    sc[i][j] = fmaf(a[i], b[j], sc[i][j]);
        }

        const bool boundary = (k0 + 63 > q0);
        #pragma unroll
        for (int i = 0; i < 8; ++i) {
            int qrow = q0 + ty*8 + i;
            #pragma unroll
            for (int j = 0; j < 4; ++j) {
                int kcol = k0 + tx + 16*j;
                sc[i][j] = (boundary && kcol > qrow) ? -INFINITY : sc[i][j]*scale;
            }
        }

        #pragma unroll
        for (int i = 0; i < 8; ++i) {
            float rm = fmaxf(fmaxf(sc[i][0], sc[i][1]), fmaxf(sc[i][2], sc[i][3]));
            #pragma unroll
            for (int off = 8; off >= 1; off >>= 1)
                rm = fmaxf(rm, __shfl_xor_sync(0xffffffffu, rm, off));
            float mn = fmaxf(m[i], rm);
            float p0[4]; float rs = 0.f;
            #pragma unroll
            for (int j = 0; j < 4; ++j) { p0[j] = __expf(sc[i][j] - mn); rs += p0[j]; }
            #pragma unroll
            for (int off = 8; off >= 1; off >>= 1)
                rs += __shfl_xor_sync(0xffffffffu, rs, off);
            float alpha = __expf(m[i] - mn);
            l[i] = l[i]*alpha + rs;
            m[i] = mn;
            #pragma unroll
            for (int j = 0; j < 4; ++j) o[i][j] *= alpha;
            #pragma unroll
            for (int j = 0; j < 4; ++j)
                Ps[(ty*8+i)*AP + tx + 16*j] = p0[j];
        }
        __syncthreads();

        #pragma unroll 4
        for (int kk = 0; kk < 64; ++kk) {
            float a[8], b[4];
            #pragma unroll
            for (int i = 0; i < 8; ++i) a[i] = Ps[(ty*8+i)*AP + kk];
            #pragma unroll
            for (int j = 0; j < 4; ++j) b[j] = Vs[kk*AP + tx + 16*j];
            #pragma unroll
            for (int i = 0; i < 8; ++i)
                #pragma unroll
                for (int j = 0; j < 4; ++j)
                    o[i][j] = fmaf(a[i], b[j], o[i][j]);
        }
    }

    const int b = bh >> 4;
    const int h = bh & 15;
    #pragma unroll
    for (int i = 0; i < 8; ++i) {
        float inv = 1.f / l[i];
        int s = q0 + ty*8 + i;
        size_t base = ((size_t)(b*SS + s))*DD + h*HDIM;
        #pragma unroll
        for (int j = 0; j < 4; ++j)
            g_att[base + tx + 16*j] = o[i][j] * inv;
    }
}

// ---------------------------------------------------------------------------
extern "C" void kernel_launch(void* const* d_in, const int* in_sizes, int n_in,
                              void* d_out, int out_size)
{
    const float* x    = (const float*)d_in[0];
    const float* cosT = (const float*)d_in[1];
    const float* sinT = (const float*)d_in[2];
    // d_in[3] = attn_mask (causal — applied analytically)
    const float* Wq = (const float*)d_in[4];
    const float* bq = (const float*)d_in[5];
    const float* Wk = (const float*)d_in[6];
    const float* bk = (const float*)d_in[7];
    const float* Wv = (const float*)d_in[8];
    const float* bv = (const float*)d_in[9];
    const float* Wo = (const float*)d_in[10];
    const float* bo = (const float*)d_in[11];
    float* out = (float*)d_out;

    qkv_gemm<<<dim3(DD/128, NT/128, 3), 256>>>(x, Wq, bq, Wk, bk, Wv, bv, cosT, sinT);

    size_t smem = (size_t)(128*AP + 64*AP + 64*AP + 128*AP) * sizeof(float);
    cudaFuncSetAttribute(attn_kernel, cudaFuncAttributeMaxDynamicSharedMemorySize, (int)smem);
    attn_kernel<<<dim3(SS/128, BB*HH), 256, smem>>>();

    out_gemm<<<dim3(DD/128, NT/128), 256>>>(Wo, bo, out);
}

// round 5
// speedup vs baseline: 3.4089x; 1.7605x over previous
#include <cuda_runtime.h>
#include <cuda_bf16.h>
#include <math.h>

#define BB 4
#define SS 2048
#define DD 1024
#define HH 16
#define HDIM 64
#define NT (BB*SS)   // 8192 tokens
#define PA 40        // gemm smem pitch (bf16 elems)
#define PK 72        // attention smem pitch (bf16 elems) — rows 4 banks apart

// Scratch (static device globals — allocation-free)
__device__ float g_q[(size_t)BB*HH*SS*HDIM];   // [b,h,s,hd]
__device__ float g_k[(size_t)BB*HH*SS*HDIM];
__device__ float g_v[(size_t)BB*HH*SS*HDIM];
__device__ float g_att[(size_t)NT*DD];          // [t, d]

#define MMA_BF16(d, a, b0, b1)                                             \
    asm("mma.sync.aligned.m16n8k16.row.col.f32.bf16.bf16.f32 "             \
        "{%0,%1,%2,%3}, {%4,%5,%6,%7}, {%8,%9}, {%0,%1,%2,%3};"            \
        : "+f"(d[0]), "+f"(d[1]), "+f"(d[2]), "+f"(d[3])                   \
        : "r"(a[0]), "r"(a[1]), "r"(a[2]), "r"(a[3]), "r"(b0), "r"(b1))

__device__ __forceinline__ void ldsm4(unsigned &r0, unsigned &r1, unsigned &r2, unsigned &r3, unsigned a) {
    asm volatile("ldmatrix.sync.aligned.m8n8.x4.shared.b16 {%0,%1,%2,%3}, [%4];"
                 : "=r"(r0), "=r"(r1), "=r"(r2), "=r"(r3) : "r"(a));
}
__device__ __forceinline__ void ldsm4t(unsigned &r0, unsigned &r1, unsigned &r2, unsigned &r3, unsigned a) {
    asm volatile("ldmatrix.sync.aligned.m8n8.x4.trans.shared.b16 {%0,%1,%2,%3}, [%4];"
                 : "=r"(r0), "=r"(r1), "=r"(r2), "=r"(r3) : "r"(a));
}
__device__ __forceinline__ unsigned smem_u32(const void* p) {
    return (unsigned)__cvta_generic_to_shared(p);
}
__device__ __forceinline__ unsigned packbf(__nv_bfloat16 a, __nv_bfloat16 b) {
    __nv_bfloat162 t(a, b);
    return reinterpret_cast<unsigned&>(t);
}

// ---------------------------------------------------------------------------
// bf16-split GEMM mainloop (unchanged from R3): out[t,n] = sum_k A[t,k]*W[n,k]
// ---------------------------------------------------------------------------
__device__ __forceinline__ void run_gemm(
    const float* __restrict__ Ag, const float* __restrict__ Wg,
    int t0, int n0,
    __nv_bfloat16* __restrict__ Ah, __nv_bfloat16* __restrict__ Al,
    __nv_bfloat16* __restrict__ Bh, __nv_bfloat16* __restrict__ Bl,
    float acc[2][8][4])
{
    const int tid  = threadIdx.x;
    const int lane = tid & 31;
    const int warp = tid >> 5;
    const int wm   = warp & 3;
    const int wn   = warp >> 2;
    const int lrow = tid >> 3;
    const int lc4  = tid & 7;

    float4 ra[4], rb[4];

    #pragma unroll
    for (int p = 0; p < 4; ++p) {
        int row = lrow + p * 32;
        ra[p] = *(const float4*)&Ag[(size_t)(t0 + row) * DD + lc4 * 4];
        rb[p] = *(const float4*)&Wg[(size_t)(n0 + row) * DD + lc4 * 4];
    }

    for (int kc = 0; kc < DD / 32; ++kc) {
        #pragma unroll
        for (int p = 0; p < 4; ++p) {
            int row = lrow + p * 32;
            float va[4] = {ra[p].x, ra[p].y, ra[p].z, ra[p].w};
            float vb[4] = {rb[p].x, rb[p].y, rb[p].z, rb[p].w};
            #pragma unroll
            for (int e = 0; e < 2; ++e) {
                __nv_bfloat16 h0 = __float2bfloat16(va[2*e]);
                __nv_bfloat16 h1 = __float2bfloat16(va[2*e+1]);
                __nv_bfloat16 l0 = __float2bfloat16(va[2*e]   - __bfloat162float(h0));
                __nv_bfloat16 l1 = __float2bfloat16(va[2*e+1] - __bfloat162float(h1));
                *(__nv_bfloat162*)&Ah[row*PA + lc4*4 + 2*e] = __nv_bfloat162(h0, h1);
                *(__nv_bfloat162*)&Al[row*PA + lc4*4 + 2*e] = __nv_bfloat162(l0, l1);
                h0 = __float2bfloat16(vb[2*e]);
                h1 = __float2bfloat16(vb[2*e+1]);
                l0 = __float2bfloat16(vb[2*e]   - __bfloat162float(h0));
                l1 = __float2bfloat16(vb[2*e+1] - __bfloat162float(h1));
                *(__nv_bfloat162*)&Bh[row*PA + lc4*4 + 2*e] = __nv_bfloat162(h0, h1);
                *(__nv_bfloat162*)&Bl[row*PA + lc4*4 + 2*e] = __nv_bfloat162(l0, l1);
            }
        }
        __syncthreads();

        if (kc + 1 < DD / 32) {
            const int k0 = (kc + 1) * 32;
            #pragma unroll
            for (int p = 0; p < 4; ++p) {
                int row = lrow + p * 32;
                ra[p] = *(const float4*)&Ag[(size_t)(t0 + row) * DD + k0 + lc4 * 4];
                rb[p] = *(const float4*)&Wg[(size_t)(n0 + row) * DD + k0 + lc4 * 4];
            }
        }

        #pragma unroll
        for (int k16 = 0; k16 < 2; ++k16) {
            const int kb = k16 * 16 + (lane & 3) * 2;
            unsigned ah[2][4], al[2][4];
            #pragma unroll
            for (int am = 0; am < 2; ++am) {
                int r0 = wm * 32 + am * 16 + (lane >> 2);
                ah[am][0] = *(const unsigned*)&Ah[ r0      * PA + kb];
                ah[am][1] = *(const unsigned*)&Ah[(r0 + 8) * PA + kb];
                ah[am][2] = *(const unsigned*)&Ah[ r0      * PA + kb + 8];
                ah[am][3] = *(const unsigned*)&Ah[(r0 + 8) * PA + kb + 8];
                al[am][0] = *(const unsigned*)&Al[ r0      * PA + kb];
                al[am][1] = *(const unsigned*)&Al[(r0 + 8) * PA + kb];
                al[am][2] = *(const unsigned*)&Al[ r0      * PA + kb + 8];
                al[am][3] = *(const unsigned*)&Al[(r0 + 8) * PA + kb + 8];
            }
            #pragma unroll
            for (int j = 0; j < 8; ++j) {
                int rn = wn * 64 + j * 8 + (lane >> 2);
                unsigned bh0 = *(const unsigned*)&Bh[rn * PA + kb];
                unsigned bh1 = *(const unsigned*)&Bh[rn * PA + kb + 8];
                unsigned bl0 = *(const unsigned*)&Bl[rn * PA + kb];
                unsigned bl1 = *(const unsigned*)&Bl[rn * PA + kb + 8];
                #pragma unroll
                for (int am = 0; am < 2; ++am) {
                    MMA_BF16(acc[am][j], ah[am], bh0, bh1);
                    MMA_BF16(acc[am][j], ah[am], bl0, bl1);
                    MMA_BF16(acc[am][j], al[am], bh0, bh1);
                }
            }
        }
        __syncthreads();
    }
}

// ---------------------------------------------------------------------------
// Kernel 1: QKV projections + bias + fused RoPE -> [b,h,s,hd] scratch.
// ---------------------------------------------------------------------------
__global__ __launch_bounds__(256) void qkv_gemm(
    const float* __restrict__ x,
    const float* __restrict__ Wq, const float* __restrict__ bq,
    const float* __restrict__ Wk, const float* __restrict__ bk,
    const float* __restrict__ Wv, const float* __restrict__ bv,
    const float* __restrict__ cosT, const float* __restrict__ sinT)
{
    __shared__ __align__(16) __nv_bfloat16 Ah[128*PA], Al[128*PA], Bh[128*PA], Bl[128*PA];

    const int z = blockIdx.z;
    const float* __restrict__ Wp = (z==0) ? Wq : (z==1) ? Wk : Wv;
    const float* __restrict__ bp = (z==0) ? bq : (z==1) ? bk : bv;
    float* __restrict__ dst      = (z==0) ? g_q : (z==1) ? g_k : g_v;

    const int t0 = blockIdx.y * 128;
    const int n0 = blockIdx.x * 128;
    const int lane = threadIdx.x & 31;
    const int warp = threadIdx.x >> 5;
    const int wm = warp & 3, wn = warp >> 2;

    float acc[2][8][4] = {};
    run_gemm(x, Wp, t0, n0, Ah, Al, Bh, Bl, acc);

    const int h = (n0 + wn * 64) >> 6;
    float2 bia[8];
    #pragma unroll
    for (int j = 0; j < 8; ++j)
        bia[j] = *(const float2*)&bp[n0 + wn*64 + j*8 + (lane & 3)*2];

    #pragma unroll
    for (int am = 0; am < 2; ++am) {
        int r0 = t0 + wm*32 + am*16 + (lane >> 2);
        #pragma unroll
        for (int half = 0; half < 2; ++half) {
            int t = r0 + half * 8;
            int b = t >> 11;
            int s = t & (SS - 1);
            size_t base = (((size_t)b*HH + h)*SS + s) * HDIM;
            if (z < 2) {
                #pragma unroll
                for (int j = 0; j < 4; ++j) {
                    int ch = j*8 + (lane & 3)*2;
                    float v0a = acc[am][j  ][2*half]   + bia[j].x;
                    float v0b = acc[am][j  ][2*half+1] + bia[j].y;
                    float v1a = acc[am][j+4][2*half]   + bia[j+4].x;
                    float v1b = acc[am][j+4][2*half+1] + bia[j+4].y;
                    float2 c0 = *(const float2*)&cosT[s*HDIM + ch];
                    float2 s0 = *(const float2*)&sinT[s*HDIM + ch];
                    float2 c1 = *(const float2*)&cosT[s*HDIM + ch + 32];
                    float2 s1 = *(const float2*)&sinT[s*HDIM + ch + 32];
                    float2 o0, o1;
                    o0.x = v0a*c0.x - v1a*s0.x;
                    o0.y = v0b*c0.y - v1b*s0.y;
                    o1.x = v1a*c1.x + v0a*s1.x;
                    o1.y = v1b*c1.y + v0b*s1.y;
                    *(float2*)&dst[base + ch]      = o0;
                    *(float2*)&dst[base + ch + 32] = o1;
                }
            } else {
                #pragma unroll
                for (int j = 0; j < 8; ++j) {
                    int ch = j*8 + (lane & 3)*2;
                    float2 o;
                    o.x = acc[am][j][2*half]   + bia[j].x;
                    o.y = acc[am][j][2*half+1] + bia[j].y;
                    *(float2*)&dst[base + ch] = o;
                }
            }
        }
    }
}

// ---------------------------------------------------------------------------
// Kernel 3: output projection -> d_out [t, n].
// ---------------------------------------------------------------------------
__global__ __launch_bounds__(256) void out_gemm(
    const float* __restrict__ Wo, const float* __restrict__ bo,
    float* __restrict__ out)
{
    __shared__ __align__(16) __nv_bfloat16 Ah[128*PA], Al[128*PA], Bh[128*PA], Bl[128*PA];

    const int t0 = blockIdx.y * 128;
    const int n0 = blockIdx.x * 128;
    const int lane = threadIdx.x & 31;
    const int warp = threadIdx.x >> 5;
    const int wm = warp & 3, wn = warp >> 2;

    float acc[2][8][4] = {};
    run_gemm(g_att, Wo, t0, n0, Ah, Al, Bh, Bl, acc);

    float2 bia[8];
    #pragma unroll
    for (int j = 0; j < 8; ++j)
        bia[j] = *(const float2*)&bo[n0 + wn*64 + j*8 + (lane & 3)*2];

    #pragma unroll
    for (int am = 0; am < 2; ++am) {
        int r0 = t0 + wm*32 + am*16 + (lane >> 2);
        #pragma unroll
        for (int half = 0; half < 2; ++half) {
            int t = r0 + half * 8;
            #pragma unroll
            for (int j = 0; j < 8; ++j) {
                int n = n0 + wn*64 + j*8 + (lane & 3)*2;
                float2 o;
                o.x = acc[am][j][2*half]   + bia[j].x;
                o.y = acc[am][j][2*half+1] + bia[j].y;
                *(float2*)&out[(size_t)t*DD + n] = o;
            }
        }
    }
}

// ---------------------------------------------------------------------------
// Kernel 2: flash causal attention on tensor cores (bf16 hi/lo split).
// 128q tile (8 warps x 16 rows) x 64k blocks. grid = (16, 64).
// ---------------------------------------------------------------------------
__global__ __launch_bounds__(256, 2) void attn_mma()
{
    extern __shared__ __align__(16) __nv_bfloat16 smb[];
    __nv_bfloat16* Qh = smb;               // [128][PK]
    __nv_bfloat16* Ql = Qh + 128*PK;
    __nv_bfloat16* Kh = Ql + 128*PK;       // [64][PK]
    __nv_bfloat16* Kl = Kh + 64*PK;
    __nv_bfloat16* Vh = Kl + 64*PK;        // [64][PK]
    __nv_bfloat16* Vl = Vh + 64*PK;

    const int tid  = threadIdx.x;
    const int lane = tid & 31;
    const int warp = tid >> 5;
    const int bh = blockIdx.y;
    const int qt = gridDim.x - 1 - blockIdx.x;   // long tiles first
    const int q0 = qt * 128;

    const float* __restrict__ qptr = g_q + (size_t)bh*SS*HDIM;
    const float* __restrict__ kptr = g_k + (size_t)bh*SS*HDIM;
    const float* __restrict__ vptr = g_v + (size_t)bh*SS*HDIM;

    // ---- load Q tile -> bf16 hi/lo smem
    #pragma unroll
    for (int p = 0; p < 8; ++p) {
        int idx = tid + p*256;
        int row = idx >> 4, c4 = idx & 15;
        float4 v = *(const float4*)&qptr[(size_t)(q0+row)*HDIM + c4*4];
        float va[4] = {v.x, v.y, v.z, v.w};
        unsigned h2[2], l2[2];
        #pragma unroll
        for (int e = 0; e < 2; ++e) {
            __nv_bfloat16 h0 = __float2bfloat16(va[2*e]);
            __nv_bfloat16 h1 = __float2bfloat16(va[2*e+1]);
            h2[e] = packbf(h0, h1);
            l2[e] = packbf(__float2bfloat16(va[2*e]   - __bfloat162float(h0)),
                           __float2bfloat16(va[2*e+1] - __bfloat162float(h1)));
        }
        *(uint2*)&Qh[row*PK + c4*4] = make_uint2(h2[0], h2[1]);
        *(uint2*)&Ql[row*PK + c4*4] = make_uint2(l2[0], l2[1]);
    }

    // ldmatrix per-lane addresses
    const int g  = lane >> 3, lr = lane & 7;
    const unsigned aQoff = (unsigned)((warp*16 + (g&1)*8 + lr)*PK + (g>>1)*8) * 2;
    const unsigned adQh = smem_u32(Qh) + aQoff;
    const unsigned adQl = smem_u32(Ql) + aQoff;
    const unsigned bKoff = (unsigned)(((g&1)*8 + lr)*PK + (g>>1)*8) * 2;
    const unsigned adKh = smem_u32(Kh) + bKoff;
    const unsigned adKl = smem_u32(Kl) + bKoff;
    const unsigned adVh = smem_u32(Vh) + bKoff;   // same pattern (row advances = k16, col = jp)
    const unsigned adVl = smem_u32(Vl) + bKoff;

    float O[8][4] = {};
    float m0 = -1e30f, m1 = -1e30f, l0 = 0.f, l1 = 0.f;
    const float C = 0.18033688011112042f;   // (1/8) * log2(e)

    const int nkb = 2*qt + 2;
    for (int kb = 0; kb < nkb; ++kb) {
        const int k0 = kb * 64;
        __syncthreads();
        // ---- load K,V block -> bf16 hi/lo smem
        #pragma unroll
        for (int p = 0; p < 4; ++p) {
            int idx = tid + p*256;
            int row = idx >> 4, c4 = idx & 15;
            float4 kv = *(const float4*)&kptr[(size_t)(k0+row)*HDIM + c4*4];
            float4 vv = *(const float4*)&vptr[(size_t)(k0+row)*HDIM + c4*4];
            float ka[4] = {kv.x, kv.y, kv.z, kv.w};
            float va[4] = {vv.x, vv.y, vv.z, vv.w};
            unsigned kh2[2], kl2[2], vh2[2], vl2[2];
            #pragma unroll
            for (int e = 0; e < 2; ++e) {
                __nv_bfloat16 h0 = __float2bfloat16(ka[2*e]);
                __nv_bfloat16 h1 = __float2bfloat16(ka[2*e+1]);
                kh2[e] = packbf(h0, h1);
                kl2[e] = packbf(__float2bfloat16(ka[2*e]   - __bfloat162float(h0)),
                                __float2bfloat16(ka[2*e+1] - __bfloat162float(h1)));
                h0 = __float2bfloat16(va[2*e]);
                h1 = __float2bfloat16(va[2*e+1]);
                vh2[e] = packbf(h0, h1);
                vl2[e] = packbf(__float2bfloat16(va[2*e]   - __bfloat162float(h0)),
                                __float2bfloat16(va[2*e+1] - __bfloat162float(h1)));
            }
            *(uint2*)&Kh[row*PK + c4*4] = make_uint2(kh2[0], kh2[1]);
            *(uint2*)&Kl[row*PK + c4*4] = make_uint2(kl2[0], kl2[1]);
            *(uint2*)&Vh[row*PK + c4*4] = make_uint2(vh2[0], vh2[1]);
            *(uint2*)&Vl[row*PK + c4*4] = make_uint2(vl2[0], vl2[1]);
        }
        __syncthreads();

        // ---- S = Q K^T (split: qh*kh + qh*kl + ql*kh)
        float z[8][4] = {};
        #pragma unroll
        for (int k16 = 0; k16 < 4; ++k16) {
            unsigned qh[4], ql[4];
            ldsm4(qh[0], qh[1], qh[2], qh[3], adQh + k16*32);
            ldsm4(ql[0], ql[1], ql[2], ql[3], adQl + k16*32);
            #pragma unroll
            for (int jp = 0; jp < 4; ++jp) {
                unsigned kh[4], kl[4];
                const unsigned off = (unsigned)(jp*16*PK + k16*16) * 2;
                ldsm4(kh[0], kh[1], kh[2], kh[3], adKh + off);
                ldsm4(kl[0], kl[1], kl[2], kl[3], adKl + off);
                // regs: {b0(j0), b0(j1), b1(j0), b1(j1)}
                MMA_BF16(z[2*jp],   qh, kh[0], kh[2]);
                MMA_BF16(z[2*jp],   qh, kl[0], kl[2]);
                MMA_BF16(z[2*jp],   ql, kh[0], kh[2]);
                MMA_BF16(z[2*jp+1], qh, kh[1], kh[3]);
                MMA_BF16(z[2*jp+1], qh, kl[1], kl[3]);
                MMA_BF16(z[2*jp+1], ql, kh[1], kh[3]);
            }
        }

        // ---- scale (log2 domain) + causal mask
        const bool tail = (kb >= 2*qt);
        #pragma unroll
        for (int j = 0; j < 8; ++j) {
            #pragma unroll
            for (int c = 0; c < 4; ++c) {
                int key = k0 + j*8 + (lane & 3)*2 + (c & 1);
                int row = q0 + warp*16 + (lane >> 2) + (c >> 1)*8;
                z[j][c] = (tail && key > row) ? -1e30f : z[j][c]*C;
            }
        }

        // ---- online softmax
        float ml0 = -1e30f, ml1 = -1e30f;
        #pragma unroll
        for (int j = 0; j < 8; ++j) {
            ml0 = fmaxf(ml0, fmaxf(z[j][0], z[j][1]));
            ml1 = fmaxf(ml1, fmaxf(z[j][2], z[j][3]));
        }
        ml0 = fmaxf(ml0, __shfl_xor_sync(0xffffffffu, ml0, 1));
        ml0 = fmaxf(ml0, __shfl_xor_sync(0xffffffffu, ml0, 2));
        ml1 = fmaxf(ml1, __shfl_xor_sync(0xffffffffu, ml1, 1));
        ml1 = fmaxf(ml1, __shfl_xor_sync(0xffffffffu, ml1, 2));
        float mn0 = fmaxf(m0, ml0), mn1 = fmaxf(m1, ml1);
        float al0 = exp2f(m0 - mn0), al1 = exp2f(m1 - mn1);
        m0 = mn0; m1 = mn1;

        float rs0 = 0.f, rs1 = 0.f;
        #pragma unroll
        for (int j = 0; j < 8; ++j) {
            z[j][0] = exp2f(z[j][0] - mn0);
            z[j][1] = exp2f(z[j][1] - mn0);
            z[j][2] = exp2f(z[j][2] - mn1);
            z[j][3] = exp2f(z[j][3] - mn1);
            rs0 += z[j][0] + z[j][1];
            rs1 += z[j][2] + z[j][3];
        }
        rs0 += __shfl_xor_sync(0xffffffffu, rs0, 1);
        rs0 += __shfl_xor_sync(0xffffffffu, rs0, 2);
        rs1 += __shfl_xor_sync(0xffffffffu, rs1, 1);
        rs1 += __shfl_xor_sync(0xffffffffu, rs1, 2);
        l0 = l0*al0 + rs0;
        l1 = l1*al1 + rs1;
        #pragma unroll
        for (int j = 0; j < 8; ++j) {
            O[j][0] *= al0; O[j][1] *= al0;
            O[j][2] *= al1; O[j][3] *= al1;
        }

        // ---- O += P V (split: ph*vh + ph*vl + pl*vh)
        #pragma unroll
        for (int k16 = 0; k16 < 4; ++k16) {
            const int f0 = 2*k16, f1 = 2*k16 + 1;
            unsigned ah[4], alr[4];
            {
                __nv_bfloat16 h00 = __float2bfloat16(z[f0][0]);
                __nv_bfloat16 h01 = __float2bfloat16(z[f0][1]);
                __nv_bfloat16 h02 = __float2bfloat16(z[f0][2]);
                __nv_bfloat16 h03 = __float2bfloat16(z[f0][3]);
                __nv_bfloat16 h10 = __float2bfloat16(z[f1][0]);
                __nv_bfloat16 h11 = __float2bfloat16(z[f1][1]);
                __nv_bfloat16 h12 = __float2bfloat16(z[f1][2]);
                __nv_bfloat16 h13 = __float2bfloat16(z[f1][3]);
                ah[0] = packbf(h00, h01);
                ah[1] = packbf(h02, h03);
                ah[2] = packbf(h10, h11);
                ah[3] = packbf(h12, h13);
                alr[0] = packbf(__float2bfloat16(z[f0][0] - __bfloat162float(h00)),
                                __float2bfloat16(z[f0][1] - __bfloat162float(h01)));
                alr[1] = packbf(__float2bfloat16(z[f0][2] - __bfloat162float(h02)),
                                __float2bfloat16(z[f0][3] - __bfloat162float(h03)));
                alr[2] = packbf(__float2bfloat16(z[f1][0] - __bfloat162float(h10)),
                                __float2bfloat16(z[f1][1] - __bfloat162float(h11)));
                alr[3] = packbf(__float2bfloat16(z[f1][2] - __bfloat162float(h12)),
                                __float2bfloat16(z[f1][3] - __bfloat162float(h13)));
            }
            #pragma unroll
            for (int jp = 0; jp < 4; ++jp) {
                unsigned vh[4], vl[4];
                const unsigned off = (unsigned)(k16*16*PK + jp*16) * 2;
                ldsm4t(vh[0], vh[1], vh[2], vh[3], adVh + off);
                ldsm4t(vl[0], vl[1], vl[2], vl[3], adVl + off);
                // regs: {b0(j0), b1(j0), b0(j1), b1(j1)}
                MMA_BF16(O[2*jp],   ah,  vh[0], vh[1]);
                MMA_BF16(O[2*jp],   ah,  vl[0], vl[1]);
                MMA_BF16(O[2*jp],   alr, vh[0], vh[1]);
                MMA_BF16(O[2*jp+1], ah,  vh[2], vh[3]);
                MMA_BF16(O[2*jp+1], ah,  vl[2], vl[3]);
                MMA_BF16(O[2*jp+1], alr, vh[2], vh[3]);
            }
        }
    }

    // ---- normalize + write [t, d]
    const int b = bh >> 4;
    const int h = bh & 15;
    const float inv0 = 1.f / l0, inv1 = 1.f / l1;
    const int rlo = q0 + warp*16 + (lane >> 2);
    #pragma unroll
    for (int j = 0; j < 8; ++j) {
        int hd = h*HDIM + j*8 + (lane & 3)*2;
        float2 o0 = make_float2(O[j][0]*inv0, O[j][1]*inv0);
        float2 o1 = make_float2(O[j][2]*inv1, O[j][3]*inv1);
        *(float2*)&g_att[((size_t)(b*SS + rlo    ))*DD + hd] = o0;
        *(float2*)&g_att[((size_t)(b*SS + rlo + 8))*DD + hd] = o1;
    }
}

// ---------------------------------------------------------------------------
extern "C" void kernel_launch(void* const* d_in, const int* in_sizes, int n_in,
                              void* d_out, int out_size)
{
    const float* x    = (const float*)d_in[0];
    const float* cosT = (const float*)d_in[1];
    const float* sinT = (const float*)d_in[2];
    // d_in[3] = attn_mask (causal — applied analytically)
    const float* Wq = (const float*)d_in[4];
    const float* bq = (const float*)d_in[5];
    const float* Wk = (const float*)d_in[6];
    const float* bk = (const float*)d_in[7];
    const float* Wv = (const float*)d_in[8];
    const float* bv = (const float*)d_in[9];
    const float* Wo = (const float*)d_in[10];
    const float* bo = (const float*)d_in[11];
    float* out = (float*)d_out;

    qkv_gemm<<<dim3(DD/128, NT/128, 3), 256>>>(x, Wq, bq, Wk, bk, Wv, bv, cosT, sinT);

    size_t smem = (size_t)(2*128*PK + 2*64*PK + 2*64*PK) * sizeof(__nv_bfloat16);  // 73728
    cudaFuncSetAttribute(attn_mma, cudaFuncAttributeMaxDynamicSharedMemorySize, (int)smem);
    attn_mma<<<dim3(SS/128, BB*HH), 256, smem>>>();

    out_gemm<<<dim3(DD/128, NT/128), 256>>>(Wo, bo, out);
}